// round 4
// baseline (speedup 1.0000x reference)
#include <cuda_runtime.h>
#include <cuda_bf16.h>

#define MAX_NODES 500000
#define MAX_EDGES 8000000
#define MAX_GRAPHS 8192
#define FDIM 16
#define SCAN_BS 1024
#define MAX_SCAN_BLOCKS 1024   // ceil(500000/1024)=489

__device__ int   g_cnt_i[MAX_NODES];          // in-degree (no self loop)
__device__ int   g_off[MAX_NODES + 1];        // CSR offsets
__device__ int   g_cursor[MAX_NODES];         // fill cursors
__device__ int   g_srcs[MAX_EDGES];           // CSR: source per (sorted-by-col) edge
__device__ int   g_part[MAX_SCAN_BLOCKS];     // scan partials
__device__ float g_dinv[MAX_NODES];
__device__ float g_h[MAX_NODES * FDIM];       // layer1 h * dinv (prescaled)
__device__ float g_h2[MAX_NODES * FDIM];      // layer2 h * dinv (prescaled)
__device__ float g_agg[MAX_NODES * FDIM];     // gather output (raw sums)
__device__ float g_pool[MAX_GRAPHS * FDIM];
__device__ float g_gcnt[MAX_GRAPHS];

__device__ __forceinline__ void red_v4(float* addr, float4 v) {
    asm volatile("red.global.add.v4.f32 [%0], {%1,%2,%3,%4};"
                 :: "l"(addr), "f"(v.x), "f"(v.y), "f"(v.z), "f"(v.w)
                 : "memory");
}

// ---- CSR build -------------------------------------------------------------
__global__ void k_zero_cnt(int N) {
    int n = blockIdx.x * blockDim.x + threadIdx.x;
    if (n < N) g_cnt_i[n] = 0;
}

__global__ void k_count(const int* __restrict__ cols, int E) {
    int e = blockIdx.x * blockDim.x + threadIdx.x;
    if (e < E) atomicAdd(&g_cnt_i[cols[e]], 1);
}

// block-level exclusive scan (Hillis-Steele), emit block totals
__global__ void k_scan1(int N) {
    __shared__ int sm[SCAN_BS];
    int tid = threadIdx.x;
    int i = blockIdx.x * SCAN_BS + tid;
    int v = (i < N) ? g_cnt_i[i] : 0;
    sm[tid] = v;
    __syncthreads();
    for (int off = 1; off < SCAN_BS; off <<= 1) {
        int t = (tid >= off) ? sm[tid - off] : 0;
        __syncthreads();
        sm[tid] += t;
        __syncthreads();
    }
    if (i < N) g_off[i] = sm[tid] - v;  // exclusive within block
    if (tid == SCAN_BS - 1) g_part[blockIdx.x] = sm[tid];
}

// single-block scan of partials (NB <= 1024)
__global__ void k_scan2(int NB) {
    __shared__ int sm[SCAN_BS];
    int tid = threadIdx.x;
    int v = (tid < NB) ? g_part[tid] : 0;
    sm[tid] = v;
    __syncthreads();
    for (int off = 1; off < SCAN_BS; off <<= 1) {
        int t = (tid >= off) ? sm[tid - off] : 0;
        __syncthreads();
        sm[tid] += t;
        __syncthreads();
    }
    if (tid < NB) g_part[tid] = sm[tid] - v;  // exclusive
}

__global__ void k_scan3(int N, int E) {
    int i = blockIdx.x * blockDim.x + threadIdx.x;
    if (i < N) {
        int v = g_off[i] + g_part[i / SCAN_BS];
        g_off[i] = v;
        g_cursor[i] = v;
    }
    if (i == 0) g_off[N] = E;
}

__global__ void k_fill(const int* __restrict__ rows, const int* __restrict__ cols,
                       int E) {
    int e = blockIdx.x * blockDim.x + threadIdx.x;
    if (e >= E) return;
    int c = cols[e];
    int p = atomicAdd(&g_cursor[c], 1);
    g_srcs[p] = rows[e];
}

__global__ void k_dinv(int N) {
    int n = blockIdx.x * blockDim.x + threadIdx.x;
    if (n < N) g_dinv[n] = rsqrtf((float)(g_cnt_i[n] + 1));
}

// ---- layer 1 dense part: g_h = (x @ W1) * dinv -----------------------------
__global__ void k_layer1(const float* __restrict__ x, const float* __restrict__ W1,
                         int N) {
    __shared__ float sx[128 * 9];
    int base = blockIdx.x * 128;
    int n = base + threadIdx.x;
    int lim = min(128, N - base) * 9;
    for (int i = threadIdx.x; i < lim; i += 128)
        sx[i] = x[(long long)base * 9 + i];
    __syncthreads();
    if (n >= N) return;
    float xi[9];
#pragma unroll
    for (int k = 0; k < 9; k++) xi[k] = sx[threadIdx.x * 9 + k];
    float di = g_dinv[n];
    float4* hp = (float4*)&g_h[n * FDIM];
#pragma unroll
    for (int q = 0; q < 4; q++) {
        float s[4];
#pragma unroll
        for (int j = 0; j < 4; j++) {
            float acc = 0.0f;
#pragma unroll
            for (int k = 0; k < 9; k++) acc += xi[k] * __ldg(&W1[k * FDIM + q * 4 + j]);
            s[j] = acc * di;
        }
        hp[q] = make_float4(s[0], s[1], s[2], s[3]);
    }
}

// ---- CSR gather: g_agg[n] = sum_{r in in(n)} H[r] + H[n]  (prescaled H) ----
// one warp per node; 8 edge-slots x 4 feature-quarters.
template <int PASS>
__global__ void k_gather(int N) {
    int warp = (blockIdx.x * blockDim.x + threadIdx.x) >> 5;
    if (warp >= N) return;
    int lane = threadIdx.x & 31;
    int q = lane & 3, slot = lane >> 2;
    const float* H = (PASS == 0) ? g_h : g_h2;
    int s0 = g_off[warp], s1 = g_off[warp + 1];
    float4 acc = make_float4(0.f, 0.f, 0.f, 0.f);
    for (int e = s0 + slot; e < s1; e += 8) {
        int r = g_srcs[e];
        float4 hv = *(const float4*)&H[r * FDIM + q * 4];
        acc.x += hv.x; acc.y += hv.y; acc.z += hv.z; acc.w += hv.w;
    }
    if (slot == 0) {  // self-loop term, add once
        float4 hv = *(const float4*)&H[warp * FDIM + q * 4];
        acc.x += hv.x; acc.y += hv.y; acc.z += hv.z; acc.w += hv.w;
    }
#pragma unroll
    for (int m = 4; m <= 16; m <<= 1) {
        acc.x += __shfl_xor_sync(0xffffffffu, acc.x, m);
        acc.y += __shfl_xor_sync(0xffffffffu, acc.y, m);
        acc.z += __shfl_xor_sync(0xffffffffu, acc.z, m);
        acc.w += __shfl_xor_sync(0xffffffffu, acc.w, m);
    }
    if (slot == 0) *(float4*)&g_agg[warp * FDIM + q * 4] = acc;
}

// ---- transform: a = relu(agg*dinv + b1); g_h2 = (a @ W2) * dinv ------------
__global__ void k_transform(const float* __restrict__ b1, const float* __restrict__ W2,
                            int N) {
    int n = blockIdx.x * blockDim.x + threadIdx.x;
    if (n >= N) return;
    float di = g_dinv[n];
    float a[FDIM];
    const float4* ain = (const float4*)&g_agg[n * FDIM];
#pragma unroll
    for (int qq = 0; qq < 4; qq++) {
        float4 v = ain[qq];
        a[qq*4+0] = fmaxf(v.x * di + __ldg(&b1[qq*4+0]), 0.0f);
        a[qq*4+1] = fmaxf(v.y * di + __ldg(&b1[qq*4+1]), 0.0f);
        a[qq*4+2] = fmaxf(v.z * di + __ldg(&b1[qq*4+2]), 0.0f);
        a[qq*4+3] = fmaxf(v.w * di + __ldg(&b1[qq*4+3]), 0.0f);
    }
    float4* hp = (float4*)&g_h2[n * FDIM];
#pragma unroll
    for (int qq = 0; qq < 4; qq++) {
        float s[4];
#pragma unroll
        for (int j = 0; j < 4; j++) {
            float acc = 0.0f;
#pragma unroll
            for (int k = 0; k < FDIM; k++) acc += a[k] * __ldg(&W2[k * FDIM + qq * 4 + j]);
            s[j] = acc * di;
        }
        hp[qq] = make_float4(s[0], s[1], s[2], s[3]);
    }
}

// ---- zero pool -------------------------------------------------------------
__global__ void k_zero_pool(int G) {
    int i = blockIdx.x * blockDim.x + threadIdx.x;
    if (i < G * FDIM) g_pool[i] = 0.0f;
    if (i < G) g_gcnt[i] = 0.0f;
}

// ---- final node features + pooled accumulation -----------------------------
__global__ void k_final_pool(const int* __restrict__ batch,
                             const float* __restrict__ b2, int N) {
    int n = blockIdx.x * blockDim.x + threadIdx.x;
    if (n >= N) return;
    float di = g_dinv[n];
    int g = batch[n];
    const float4* ain = (const float4*)&g_agg[n * FDIM];
#pragma unroll
    for (int qq = 0; qq < 4; qq++) {
        float4 v = ain[qq];
        float4 r = make_float4(fmaxf(v.x * di + __ldg(&b2[qq*4+0]), 0.0f),
                               fmaxf(v.y * di + __ldg(&b2[qq*4+1]), 0.0f),
                               fmaxf(v.z * di + __ldg(&b2[qq*4+2]), 0.0f),
                               fmaxf(v.w * di + __ldg(&b2[qq*4+3]), 0.0f));
        red_v4(&g_pool[g * FDIM + qq * 4], r);
    }
    atomicAdd(&g_gcnt[g], 1.0f);
}

// ---- MLP head --------------------------------------------------------------
__global__ void k_mlp(const float* __restrict__ meta,
                      const float* __restrict__ Wh1, const float* __restrict__ bh1,
                      const float* __restrict__ Wh2, const float* __restrict__ bh2,
                      float* __restrict__ out, int G) {
    int g = blockIdx.x * blockDim.x + threadIdx.x;
    if (g >= G) return;
    float inv = 1.0f / fmaxf(g_gcnt[g], 1.0f);
    float z[FDIM];
#pragma unroll
    for (int f = 0; f < FDIM; f++) z[f] = __ldg(&bh1[f]);
#pragma unroll
    for (int k = 0; k < FDIM; k++) {
        float e = g_pool[g * FDIM + k] * inv;
#pragma unroll
        for (int f = 0; f < FDIM; f++) z[f] += e * __ldg(&Wh1[k * FDIM + f]);
    }
    for (int k = 0; k < 27; k++) {
        float m = meta[g * 27 + k];
#pragma unroll
        for (int f = 0; f < FDIM; f++) z[f] += m * __ldg(&Wh1[(FDIM + k) * FDIM + f]);
    }
    float o = __ldg(&bh2[0]);
#pragma unroll
    for (int f = 0; f < FDIM; f++) o += fmaxf(z[f], 0.0f) * __ldg(&Wh2[f]);
    out[g] = o;
}

extern "C" void kernel_launch(void* const* d_in, const int* in_sizes, int n_in,
                              void* d_out, int out_size) {
    const float* x    = (const float*)d_in[0];
    const int*   ei   = (const int*)d_in[1];
    const int*   batch= (const int*)d_in[2];
    const float* meta = (const float*)d_in[3];
    const float* W1   = (const float*)d_in[4];
    const float* b1   = (const float*)d_in[5];
    const float* W2   = (const float*)d_in[6];
    const float* b2   = (const float*)d_in[7];
    const float* Wh1  = (const float*)d_in[8];
    const float* bh1  = (const float*)d_in[9];
    const float* Wh2  = (const float*)d_in[10];
    const float* bh2  = (const float*)d_in[11];
    float* out = (float*)d_out;

    const int N = in_sizes[0] / 9;
    const int E = in_sizes[1] / 2;
    const int G = in_sizes[3] / 27;
    const int* rows = ei;      // source
    const int* cols = ei + E;  // target

    const int B = 256;
    const int NB_SCAN = (N + SCAN_BS - 1) / SCAN_BS;

    // CSR build + degrees
    k_zero_cnt<<<(N + B - 1) / B, B>>>(N);
    k_count<<<(E + B - 1) / B, B>>>(cols, E);
    k_scan1<<<NB_SCAN, SCAN_BS>>>(N);
    k_scan2<<<1, SCAN_BS>>>(NB_SCAN);
    k_scan3<<<(N + B - 1) / B, B>>>(N, E);
    k_fill<<<(E + B - 1) / B, B>>>(rows, cols, E);
    k_dinv<<<(N + B - 1) / B, B>>>(N);

    // layer 1
    k_layer1<<<(N + 127) / 128, 128>>>(x, W1, N);
    {
        long long t = (long long)N * 32;
        k_gather<0><<<(int)((t + B - 1) / B), B>>>(N);
    }
    k_transform<<<(N + B - 1) / B, B>>>(b1, W2, N);

    // layer 2
    {
        long long t = (long long)N * 32;
        k_gather<1><<<(int)((t + B - 1) / B), B>>>(N);
    }

    // pooling + head
    k_zero_pool<<<(G * FDIM + B - 1) / B, B>>>(G);
    k_final_pool<<<(N + B - 1) / B, B>>>(batch, b2, N);
    k_mlp<<<(G + B - 1) / B, B>>>(meta, Wh1, bh1, Wh2, bh2, out, G);
}